// round 10
// baseline (speedup 1.0000x reference)
#include <cuda_runtime.h>
#include <cstdint>

#define BATCH 8
#define NA 184320
#define NG 64
#define T 8
#define THREADS 256
#define APB (THREADS * T)            // 2048 anchors per block
#define BLOCKS_PER_B (NA / APB)      // 90
#define BA ((long long)BATCH * NA)   // 1474560
#define GCHUNK 8                     // g's per reduction chunk (== warps per block)

__device__ unsigned long long g_best[BATCH * NG];   // static zero-init; finalize re-zeros

__global__ __launch_bounds__(THREADS, 2) void assign_kernel(
    const float* __restrict__ anchors,   // [B, A, 4] cxcywh
    const float* __restrict__ gt,        // [B, G, 4] xyxy
    float* __restrict__ out)
{
    const int b = blockIdx.y;
    const int base = blockIdx.x * APB;
    const int tid = threadIdx.x;

    __shared__ float sgx1[NG], sgy1[NG], sgx2[NG], sgy2[NG], sga[NG];
    // Double-buffered thread winners: (wi, ws) + 1-byte slot index wt.
    __shared__ float2        sWin[2][GCHUNK][THREADS];   // 32 KB
    __shared__ unsigned char sWt [2][GCHUNK][THREADS];   //  4 KB

    if (tid < NG) {
        float4 gb = ((const float4*)gt)[b * NG + tid];
        sgx1[tid] = gb.x; sgy1[tid] = gb.y;
        sgx2[tid] = gb.z; sgy2[tid] = gb.w;
        sga[tid] = (gb.z - gb.x) * (gb.w - gb.y);
    }
    __syncthreads();

    // Load T anchors per thread (stride THREADS -> coalesced)
    float x1[T], y1[T], x2[T], y2[T], ar[T];
#pragma unroll
    for (int t = 0; t < T; t++) {
        int a = base + t * THREADS + tid;
        float4 an = ((const float4*)anchors)[(long long)b * NA + a];
        float hw = 0.5f * an.z, hh = 0.5f * an.w;
        x1[t] = an.x - hw; y1[t] = an.y - hh;
        x2[t] = an.x + hw; y2[t] = an.y + hh;
        ar[t] = an.z * an.w;
    }

    // Row-max per anchor, s-form: iou ordering == (inter/s) ordering since
    // iou = i/(s-i) is monotone in i/s.  Track (bi = best inter, bs = its s).
    // bu is reconstructed later as bs - bi (bit-identical to the old uni calc).
    float bi[T], bs[T]; int bgi[T];
#pragma unroll
    for (int t = 0; t < T; t++) { bi[t] = 0.f; bs[t] = 1.f; bgi[t] = 0; }

    for (int c = 0; c < NG / GCHUNK; c++) {
        const int p = c & 1;
#pragma unroll
        for (int gg = 0; gg < GCHUNK; gg++) {
            const int g = c * GCHUNK + gg;
            const float gx1 = sgx1[g], gy1 = sgy1[g], gx2 = sgx2[g], gy2 = sgy2[g], ga = sga[g];

            float iv[T], sv[T];
#pragma unroll
            for (int t = 0; t < T; t++) {
                float w = fminf(x2[t], gx2) - fmaxf(x1[t], gx1);
                float h = fminf(y2[t], gy2) - fmaxf(y1[t], gy1);
                // only w clamped: if h<0 then inter<=0, which can never win a
                // strict-> compare against nonnegative state (bi>=0, s>0).
                float inter = fmaxf(w, 0.f) * h;
                float s = ar[t] + ga;
                iv[t] = inter; sv[t] = s;
                bool cc = inter * bs[t] > bi[t] * s;   // i/s cross-mult
                bi[t]  = cc ? inter : bi[t];
                bs[t]  = cc ? s     : bs[t];
                bgi[t] = cc ? g     : bgi[t];
            }

            // Thread-local column winner: depth-3 tree, strict > ascending index
            float ti0, tu0, ti1, tu1, ti2, tu2, ti3, tu3;
            int   tt0, tt1, tt2, tt3;
            {
                bool c01 = iv[1] * sv[0] > iv[0] * sv[1];
                ti0 = c01 ? iv[1] : iv[0]; tu0 = c01 ? sv[1] : sv[0]; tt0 = c01 ? 1 : 0;
                bool c23 = iv[3] * sv[2] > iv[2] * sv[3];
                ti1 = c23 ? iv[3] : iv[2]; tu1 = c23 ? sv[3] : sv[2]; tt1 = c23 ? 3 : 2;
                bool c45 = iv[5] * sv[4] > iv[4] * sv[5];
                ti2 = c45 ? iv[5] : iv[4]; tu2 = c45 ? sv[5] : sv[4]; tt2 = c45 ? 5 : 4;
                bool c67 = iv[7] * sv[6] > iv[6] * sv[7];
                ti3 = c67 ? iv[7] : iv[6]; tu3 = c67 ? sv[7] : sv[6]; tt3 = c67 ? 7 : 6;
            }
            float ai, au, bi2, bu2; int at, bt;
            {
                bool cA = ti1 * tu0 > ti0 * tu1;
                ai = cA ? ti1 : ti0; au = cA ? tu1 : tu0; at = cA ? tt1 : tt0;
                bool cB = ti3 * tu2 > ti2 * tu3;
                bi2 = cB ? ti3 : ti2; bu2 = cB ? tu3 : tu2; bt = cB ? tt3 : tt2;
            }
            float wi, ws; int wt;
            {
                bool cF = bi2 * au > ai * bu2;
                wi = cF ? bi2 : ai; ws = cF ? bu2 : au; wt = cF ? bt : at;
            }
            sWin[p][gg][tid] = make_float2(wi, ws);
            sWt [p][gg][tid] = (unsigned char)wt;
        }
        __syncthreads();

        // Warp w reduces g = c*GCHUNK + w over the 256 thread winners from buf p.
        // No trailing barrier: fast warps proceed into main(c+1), which writes
        // buf p^1; buf p is next written at main(c+2), after sync(c+1).
        {
            const int gg = tid >> 5;
            const int lane = tid & 31;
            float2 v0 = sWin[p][gg][lane];
            int    x0 = base + (int)sWt[p][gg][lane] * THREADS + lane;
            float wi = v0.x, ws = v0.y; int wx = x0;
#pragma unroll
            for (int k = 1; k < 8; k++) {
                const int j = k * 32 + lane;
                float2 v = sWin[p][gg][j];
                int    x = base + (int)sWt[p][gg][j] * THREADS + j;
                bool cc = v.x * ws > wi * v.y;
                wi = cc ? v.x : wi; ws = cc ? v.y : ws; wx = cc ? x : wx;
            }
#pragma unroll
            for (int off = 16; off; off >>= 1) {
                float oi = __shfl_down_sync(0xFFFFFFFFu, wi, off);
                float os = __shfl_down_sync(0xFFFFFFFFu, ws, off);
                int   ox = __shfl_down_sync(0xFFFFFFFFu, wx, off);
                bool cc = oi * ws > wi * os;
                wi = cc ? oi : wi; ws = cc ? os : ws; wx = cc ? ox : wx;
            }
            if (lane == 0) {
                float iou = (wi > 0.f) ? (wi / (ws - wi)) : 0.f;
                unsigned long long key =
                    ((unsigned long long)__float_as_uint(iou) << 32) |
                    (unsigned int)(~(unsigned int)wx);  // larger key = higher iou; tie -> smaller idx
                atomicMax(&g_best[b * NG + c * GCHUNK + gg], key);
            }
        }
    }

    __syncthreads();   // protect sgx/sgy reads below vs nothing; cheap, keeps order sane

    // Per-anchor outputs (bu reconstructed bit-identically: bs - bi == old uni)
#pragma unroll
    for (int t = 0; t < T; t++) {
        int a = base + t * THREADS + tid;
        long long idx = (long long)b * NA + a;
        float bu = bs[t] - bi[t];
        float miou = (bi[t] > 0.f) ? (bi[t] / bu) : 0.f;
        bool fg = miou > 0.7f;
        bool bgd = miou < 0.3f;
        bool cross = (x1[t] < 0.f) | (y1[t] < 0.f) | (x2[t] > 640.f) | (y2[t] > 640.f);
        float lab = cross ? -1.f : (fg ? 1.f : (bgd ? 0.f : -1.f));
        out[idx] = lab;                       // labels region
        int g = bgi[t];
        float4 m;
        m.x = fg ? sgx1[g] : 0.f;
        m.y = fg ? sgy1[g] : 0.f;
        m.z = fg ? sgx2[g] : 0.f;
        m.w = fg ? sgy2[g] : 0.f;
        ((float4*)(out + BA))[idx] = m;       // matched region
        out[5 * BA + idx] = miou;             // max_iou region
    }
}

// Parallel rule-1 scatter: one thread per (b, g). Last-gt-wins is enforced by a
// duplicate scan (thread g writes its matched box only if no g' > g in the same
// batch picked the same anchor). Rule-2 fg override: skip the matched write when
// the anchor's ROW max-iou (out[5*BA+idx], written by assign) > 0.7. Labels
// writes are idempotent (all writers store 1.0f). Resets g_best for next replay.
__global__ void finalize_kernel(const float* __restrict__ anchors,
                                const float* __restrict__ gt,
                                float* __restrict__ out)
{
    __shared__ int sA[BATCH * NG];
    const int tid = threadIdx.x;          // 0..511
    const int b = tid >> 6;
    const int g = tid & (NG - 1);

    unsigned long long key = g_best[tid];
    g_best[tid] = 0ull;                   // reset for next launch
    const int a = (int)(~((unsigned int)key));
    sA[tid] = a;
    __syncthreads();

    // suppressed if a later gt in this batch picked the same anchor
    bool suppressed = false;
#pragma unroll 1
    for (int gp = g + 1; gp < NG; gp++)
        suppressed |= (sA[(b << 6) + gp] == a);

    const long long idx = (long long)b * NA + a;
    float4 an = ((const float4*)anchors)[(long long)b * NA + a];
    float hw = 0.5f * an.z, hh = 0.5f * an.w;
    float ax1 = an.x - hw, ay1 = an.y - hh, ax2 = an.x + hw, ay2 = an.y + hh;
    bool cross = (ax1 < 0.f) | (ay1 < 0.f) | (ax2 > 640.f) | (ay2 > 640.f);

    if (!cross) out[idx] = 1.f;           // rule 1 label (cross filter wins at end)

    float rowmax = out[5 * BA + idx];     // anchor's max-iou over all gts (rule-2 fg cond)
    if (!(rowmax > 0.7f) && !suppressed) {
        float4 gb = ((const float4*)gt)[b * NG + g];
        ((float4*)(out + BA))[idx] = gb;
    }
}

extern "C" void kernel_launch(void* const* d_in, const int* in_sizes, int n_in,
                              void* d_out, int out_size)
{
    const float* anchors = (const float*)d_in[0];
    const float* gtb     = (const float*)d_in[1];
    // Defensive: identify by size (anchors = B*A*4 = 5898240, gt = B*G*4 = 2048)
    if (n_in >= 2 && in_sizes[0] == BATCH * NG * 4) {
        anchors = (const float*)d_in[1];
        gtb     = (const float*)d_in[0];
    }
    float* out = (float*)d_out;

    dim3 grid(BLOCKS_PER_B, BATCH);
    assign_kernel<<<grid, THREADS>>>(anchors, gtb, out);
    finalize_kernel<<<1, BATCH * NG>>>(anchors, gtb, out);
}

// round 11
// speedup vs baseline: 1.6474x; 1.6474x over previous
#include <cuda_runtime.h>
#include <cstdint>

#define BATCH 8
#define NA 184320
#define NG 64
#define T 8
#define THREADS 256
#define APB (THREADS * T)            // 2048 anchors per block
#define BLOCKS_PER_B (NA / APB)      // 90
#define BA ((long long)BATCH * NA)   // 1474560
#define GCHUNK 8                     // g's per reduction chunk (== warps per block)

__device__ unsigned long long g_best[BATCH * NG];   // static zero-init; finalize re-zeros

__global__ __launch_bounds__(THREADS, 2) void assign_kernel(
    const float* __restrict__ anchors,   // [B, A, 4] cxcywh
    const float* __restrict__ gt,        // [B, G, 4] xyxy
    float* __restrict__ out)
{
    const int b = blockIdx.y;
    const int base = blockIdx.x * APB;
    const int tid = threadIdx.x;

    __shared__ float sgx1[NG], sgy1[NG], sgx2[NG], sgy2[NG], sga[NG];
    __shared__ float2 sWin[GCHUNK][THREADS];   // (wi, ws) thread winners
    __shared__ int    sWx [GCHUNK][THREADS];

    if (tid < NG) {
        float4 gb = ((const float4*)gt)[b * NG + tid];
        sgx1[tid] = gb.x; sgy1[tid] = gb.y;
        sgx2[tid] = gb.z; sgy2[tid] = gb.w;
        sga[tid] = (gb.z - gb.x) * (gb.w - gb.y);
    }
    __syncthreads();

    // Load T anchors per thread (stride THREADS -> coalesced)
    float x1[T], y1[T], x2[T], y2[T], ar[T];
#pragma unroll
    for (int t = 0; t < T; t++) {
        int a = base + t * THREADS + tid;
        float4 an = ((const float4*)anchors)[(long long)b * NA + a];
        float hw = 0.5f * an.z, hh = 0.5f * an.w;
        x1[t] = an.x - hw; y1[t] = an.y - hh;
        x2[t] = an.x + hw; y2[t] = an.y + hh;
        ar[t] = an.z * an.w;
    }

    // Row-max per anchor, s-form: iou ordering == ordering by i/s cross-mult,
    // since iou_a > iou_b  <=>  i_a*s_b > i_b*s_a (s = area_a + area_g).
    // bu is reconstructed later as bs - bi (bit-identical to the old uni calc).
    float bi[T], bs[T]; int bgi[T];
#pragma unroll
    for (int t = 0; t < T; t++) { bi[t] = 0.f; bs[t] = 1.f; bgi[t] = 0; }

    for (int c = 0; c < NG / GCHUNK; c++) {
#pragma unroll
        for (int gg = 0; gg < GCHUNK; gg++) {
            const int g = c * GCHUNK + gg;
            const float gx1 = sgx1[g], gy1 = sgy1[g], gx2 = sgx2[g], gy2 = sgy2[g], ga = sga[g];

            float iv[T], sv[T];
#pragma unroll
            for (int t = 0; t < T; t++) {
                float w = fminf(x2[t], gx2) - fmaxf(x1[t], gx1);
                float h = fminf(y2[t], gy2) - fmaxf(y1[t], gy1);
                // only w clamped: if h<0 then inter<=0, which can never win a
                // strict-> compare against nonnegative state (bi>=0, s>0).
                float inter = fmaxf(w, 0.f) * h;
                float s = ar[t] + ga;
                iv[t] = inter; sv[t] = s;
                bool cc = inter * bs[t] > bi[t] * s;
                bi[t]  = cc ? inter : bi[t];
                bs[t]  = cc ? s     : bs[t];
                bgi[t] = cc ? g     : bgi[t];
            }

            // Thread-local column winner: depth-3 tree, strict > ascending index
            float ti0, tu0, ti1, tu1, ti2, tu2, ti3, tu3;
            int   tt0, tt1, tt2, tt3;
            {
                bool c01 = iv[1] * sv[0] > iv[0] * sv[1];
                ti0 = c01 ? iv[1] : iv[0]; tu0 = c01 ? sv[1] : sv[0]; tt0 = c01 ? 1 : 0;
                bool c23 = iv[3] * sv[2] > iv[2] * sv[3];
                ti1 = c23 ? iv[3] : iv[2]; tu1 = c23 ? sv[3] : sv[2]; tt1 = c23 ? 3 : 2;
                bool c45 = iv[5] * sv[4] > iv[4] * sv[5];
                ti2 = c45 ? iv[5] : iv[4]; tu2 = c45 ? sv[5] : sv[4]; tt2 = c45 ? 5 : 4;
                bool c67 = iv[7] * sv[6] > iv[6] * sv[7];
                ti3 = c67 ? iv[7] : iv[6]; tu3 = c67 ? sv[7] : sv[6]; tt3 = c67 ? 7 : 6;
            }
            float ai, au, bi2, bu2; int at, bt;
            {
                bool cA = ti1 * tu0 > ti0 * tu1;
                ai = cA ? ti1 : ti0; au = cA ? tu1 : tu0; at = cA ? tt1 : tt0;
                bool cB = ti3 * tu2 > ti2 * tu3;
                bi2 = cB ? ti3 : ti2; bu2 = cB ? tu3 : tu2; bt = cB ? tt3 : tt2;
            }
            float wi, ws; int wt;
            {
                bool cF = bi2 * au > ai * bu2;
                wi = cF ? bi2 : ai; ws = cF ? bu2 : au; wt = cF ? bt : at;
            }
            sWin[gg][tid] = make_float2(wi, ws);
            sWx[gg][tid]  = base + wt * THREADS + tid;
        }
        __syncthreads();

        // Warp w reduces g = c*GCHUNK + w over the 256 thread winners
        {
            const int gg = tid >> 5;
            const int lane = tid & 31;
            float2 v0 = sWin[gg][lane];
            int    x0 = sWx[gg][lane];
            float wi = v0.x, ws = v0.y; int wx = x0;
#pragma unroll
            for (int k = 1; k < 8; k++) {
                float2 v = sWin[gg][k * 32 + lane];
                int    x = sWx[gg][k * 32 + lane];
                bool cc = v.x * ws > wi * v.y;
                wi = cc ? v.x : wi; ws = cc ? v.y : ws; wx = cc ? x : wx;
            }
#pragma unroll
            for (int off = 16; off; off >>= 1) {
                float oi = __shfl_down_sync(0xFFFFFFFFu, wi, off);
                float os = __shfl_down_sync(0xFFFFFFFFu, ws, off);
                int   ox = __shfl_down_sync(0xFFFFFFFFu, wx, off);
                bool cc = oi * ws > wi * os;
                wi = cc ? oi : wi; ws = cc ? os : ws; wx = cc ? ox : wx;
            }
            if (lane == 0) {
                float iou = (wi > 0.f) ? (wi / (ws - wi)) : 0.f;
                unsigned long long key =
                    ((unsigned long long)__float_as_uint(iou) << 32) |
                    (unsigned int)(~(unsigned int)wx);  // larger key = higher iou; tie -> smaller idx
                atomicMax(&g_best[b * NG + c * GCHUNK + gg], key);
            }
        }
        __syncthreads();
    }

    // Per-anchor outputs (bu reconstructed bit-identically: bs - bi == old uni)
#pragma unroll
    for (int t = 0; t < T; t++) {
        int a = base + t * THREADS + tid;
        long long idx = (long long)b * NA + a;
        float bu = bs[t] - bi[t];
        float miou = (bi[t] > 0.f) ? (bi[t] / bu) : 0.f;
        bool fg = miou > 0.7f;
        bool bgd = miou < 0.3f;
        bool cross = (x1[t] < 0.f) | (y1[t] < 0.f) | (x2[t] > 640.f) | (y2[t] > 640.f);
        float lab = cross ? -1.f : (fg ? 1.f : (bgd ? 0.f : -1.f));
        out[idx] = lab;                       // labels region
        int g = bgi[t];
        float4 m;
        m.x = fg ? sgx1[g] : 0.f;
        m.y = fg ? sgy1[g] : 0.f;
        m.z = fg ? sgx2[g] : 0.f;
        m.w = fg ? sgy2[g] : 0.f;
        ((float4*)(out + BA))[idx] = m;       // matched region
        out[5 * BA + idx] = miou;             // max_iou region
    }
}

// Parallel rule-1 scatter: one thread per (b, g). Last-gt-wins is enforced by a
// duplicate scan (thread g writes its matched box only if no g' > g in the same
// batch picked the same anchor). Rule-2 fg override: skip the matched write when
// the anchor's ROW max-iou (out[5*BA+idx], written by assign) > 0.7. Labels
// writes are idempotent (all writers store 1.0f). Resets g_best for next replay.
__global__ void finalize_kernel(const float* __restrict__ anchors,
                                const float* __restrict__ gt,
                                float* __restrict__ out)
{
    __shared__ int sA[BATCH * NG];
    const int tid = threadIdx.x;          // 0..511
    const int b = tid >> 6;
    const int g = tid & (NG - 1);

    unsigned long long key = g_best[tid];
    g_best[tid] = 0ull;                   // reset for next launch
    const int a = (int)(~((unsigned int)key));
    sA[tid] = a;
    __syncthreads();

    // suppressed if a later gt in this batch picked the same anchor
    bool suppressed = false;
#pragma unroll 1
    for (int gp = g + 1; gp < NG; gp++)
        suppressed |= (sA[(b << 6) + gp] == a);

    const long long idx = (long long)b * NA + a;
    float4 an = ((const float4*)anchors)[(long long)b * NA + a];
    float hw = 0.5f * an.z, hh = 0.5f * an.w;
    float ax1 = an.x - hw, ay1 = an.y - hh, ax2 = an.x + hw, ay2 = an.y + hh;
    bool cross = (ax1 < 0.f) | (ay1 < 0.f) | (ax2 > 640.f) | (ay2 > 640.f);

    if (!cross) out[idx] = 1.f;           // rule 1 label (cross filter wins at end)

    float rowmax = out[5 * BA + idx];     // anchor's max-iou over all gts (rule-2 fg cond)
    if (!(rowmax > 0.7f) && !suppressed) {
        float4 gb = ((const float4*)gt)[b * NG + g];
        ((float4*)(out + BA))[idx] = gb;
    }
}

extern "C" void kernel_launch(void* const* d_in, const int* in_sizes, int n_in,
                              void* d_out, int out_size)
{
    const float* anchors = (const float*)d_in[0];
    const float* gtb     = (const float*)d_in[1];
    // Defensive: identify by size (anchors = B*A*4 = 5898240, gt = B*G*4 = 2048)
    if (n_in >= 2 && in_sizes[0] == BATCH * NG * 4) {
        anchors = (const float*)d_in[1];
        gtb     = (const float*)d_in[0];
    }
    float* out = (float*)d_out;

    dim3 grid(BLOCKS_PER_B, BATCH);
    assign_kernel<<<grid, THREADS>>>(anchors, gtb, out);
    finalize_kernel<<<1, BATCH * NG>>>(anchors, gtb, out);
}